// round 12
// baseline (speedup 1.0000x reference)
#include <cuda_runtime.h>
#include <cuda_fp16.h>
#include <cstdint>

#define NB 4096
#define N2 8192
#define DD 256
#define INV_TEMP 2.0f
#define EX2_SCALE 2.885390081777927f   // 2 * log2(e)

#define BM 128
#define BN 128
#define BK 64
#define NSTRIPE (N2 / BN)        // 64 column stripes
#define NTILE 64
#define NCTA 1056                // sum over bi of (32 - bi/2)

// smem layout (bytes)
#define A_STRIDE_H 264                    // halves per A row (528 B, odd 16B units)
#define A_BYTES   (128 * A_STRIDE_H * 2)  // 67584
#define PADK 72                           // halves per B chunk row
#define B_CHUNK_BYTES (128 * PADK * 2)    // 18432
#define B_OFF     A_BYTES
#define RED_OFF   (A_BYTES + 2 * B_CHUNK_BYTES)   // 104448
#define SMEM_TOTAL (RED_OFF + 2048)               // 106496

// Scratch (static device globals — no allocation)
__device__ __half         g_zh[(size_t)N2 * DD];            // normalized rows fp16
__device__ float          g_partial[(size_t)NSTRIPE * N2];  // [stripe][row] exp-sums (diag masked)
__device__ float          g_pos[N2];                        // positive-pair sims
__device__ float          g_loss[N2];
__device__ int            g_sem;

__device__ __forceinline__ uint32_t smem_u32(const void* p) {
    return (uint32_t)__cvta_generic_to_shared(p);
}

__device__ __forceinline__ void ldsm_x4(uint32_t addr, uint32_t& r0, uint32_t& r1,
                                        uint32_t& r2, uint32_t& r3) {
    asm volatile("ldmatrix.sync.aligned.m8n8.x4.shared.b16 {%0,%1,%2,%3}, [%4];"
                 : "=r"(r0), "=r"(r1), "=r"(r2), "=r"(r3) : "r"(addr));
}

__device__ __forceinline__ void mma_f16acc(uint32_t* d, const uint32_t* a, const uint32_t* b) {
    asm volatile(
        "mma.sync.aligned.m16n8k16.row.col.f16.f16.f16.f16 "
        "{%0,%1}, {%2,%3,%4,%5}, {%6,%7}, {%0,%1};"
        : "+r"(d[0]), "+r"(d[1])
        : "r"(a[0]), "r"(a[1]), "r"(a[2]), "r"(a[3]), "r"(b[0]), "r"(b[1]));
}

__device__ __forceinline__ uint32_t h2ex2(uint32_t x) {
    uint32_t y;
    asm("ex2.approx.f16x2 %0, %1;" : "=r"(y) : "r"(x));
    return y;
}
__device__ __forceinline__ uint32_t h2mul(uint32_t a, uint32_t b) {
    __half2 r = __hmul2(*(__half2*)&a, *(__half2*)&b);
    return *(uint32_t*)&r;
}
__device__ __forceinline__ uint32_t h2add(uint32_t a, uint32_t b) {
    __half2 r = __hadd2(*(__half2*)&a, *(__half2*)&b);
    return *(uint32_t*)&r;
}

__device__ __forceinline__ void cp_async16(uint32_t smem_addr, const void* gptr) {
    asm volatile("cp.async.cg.shared.global [%0], [%1], 16;"
                 :: "r"(smem_addr), "l"(gptr) : "memory");
}
#define CP_COMMIT() asm volatile("cp.async.commit_group;" ::: "memory")
#define CP_WAIT(n)  asm volatile("cp.async.wait_group %0;" :: "n"(n) : "memory")

// ---------------------------------------------------------------------------
// Kernel 1: L2-normalize. One warp handles rows (w, w+NB).
// ---------------------------------------------------------------------------
__global__ void k_normalize(const float* __restrict__ xi, const float* __restrict__ xj) {
    int w    = blockIdx.x * 8 + (threadIdx.x >> 5);
    int lane = threadIdx.x & 31;
    const float* sa = xi + (size_t)w * DD;
    const float* sb = xj + (size_t)w * DD;
    float4 a0 = *(const float4*)(sa + lane * 4);
    float4 a1 = *(const float4*)(sa + 128 + lane * 4);
    float4 b0 = *(const float4*)(sb + lane * 4);
    float4 b1 = *(const float4*)(sb + 128 + lane * 4);
    float s_a = a0.x*a0.x + a0.y*a0.y + a0.z*a0.z + a0.w*a0.w
              + a1.x*a1.x + a1.y*a1.y + a1.z*a1.z + a1.w*a1.w;
    float s_b = b0.x*b0.x + b0.y*b0.y + b0.z*b0.z + b0.w*b0.w
              + b1.x*b1.x + b1.y*b1.y + b1.z*b1.z + b1.w*b1.w;
    #pragma unroll
    for (int o = 16; o > 0; o >>= 1) {
        s_a += __shfl_xor_sync(0xffffffffu, s_a, o);
        s_b += __shfl_xor_sync(0xffffffffu, s_b, o);
    }
    float ia = 1.0f / fmaxf(sqrtf(s_a), 1e-12f);
    float ib = 1.0f / fmaxf(sqrtf(s_b), 1e-12f);

    __half2 h[4];
    h[0] = __floats2half2_rn(a0.x * ia, a0.y * ia);
    h[1] = __floats2half2_rn(a0.z * ia, a0.w * ia);
    h[2] = __floats2half2_rn(a1.x * ia, a1.y * ia);
    h[3] = __floats2half2_rn(a1.z * ia, a1.w * ia);
    __half* da = g_zh + (size_t)w * DD;
    *(uint2*)(da + lane * 4)       = make_uint2(*(uint32_t*)&h[0], *(uint32_t*)&h[1]);
    *(uint2*)(da + 128 + lane * 4) = make_uint2(*(uint32_t*)&h[2], *(uint32_t*)&h[3]);

    h[0] = __floats2half2_rn(b0.x * ib, b0.y * ib);
    h[1] = __floats2half2_rn(b0.z * ib, b0.w * ib);
    h[2] = __floats2half2_rn(b1.x * ib, b1.y * ib);
    h[3] = __floats2half2_rn(b1.z * ib, b1.w * ib);
    __half* db = g_zh + (size_t)(w + NB) * DD;
    *(uint2*)(db + lane * 4)       = make_uint2(*(uint32_t*)&h[0], *(uint32_t*)&h[1]);
    *(uint2*)(db + 128 + lane * 4) = make_uint2(*(uint32_t*)&h[2], *(uint32_t*)&h[3]);
}

// ---------------------------------------------------------------------------
// Kernel 2: A-resident pair-tile HMMA. Each CTA holds A (128 rows, full K)
// in smem and processes up to two 128x128 sub-tiles (paired columns),
// streaming B in double-buffered K=64 chunks.
// ---------------------------------------------------------------------------
__global__ __launch_bounds__(128, 2) void k_expsum_mma() {
    extern __shared__ char smem[];
    int tid   = threadIdx.x;
    int lane  = tid & 31;
    int wid   = tid >> 5;
    int warpM = wid >> 1;
    int warpN = wid & 1;

    // Decode blockIdx.x -> (bi, pair t). Pairs per bi: 32 - (bi>>1).
    int rem = blockIdx.x;
    int bi = 0;
    while (true) {
        int p = 32 - (bi >> 1);
        if (rem < p) break;
        rem -= p; ++bi;
    }
    int t = (bi >> 1) + rem;
    int r0 = bi * BM;

    int bjs[2]; int ns = 0;
    if (2 * t >= bi) bjs[ns++] = 2 * t;
    bjs[ns++] = 2 * t + 1;

    uint32_t sbase = smem_u32(smem);
    int lrow  = tid >> 3;              // 0..15
    int lcol8 = (tid & 7) * 8;         // halves

    // --- load A (full K) ---
    {
        const __half* gA = g_zh + (size_t)r0 * DD;
        #pragma unroll
        for (int i = 0; i < 8; ++i) {
            int row = lrow + i * 16;
            #pragma unroll
            for (int c = 0; c < 4; ++c) {
                int col = lcol8 + c * 64;   // halves 0..255
                cp_async16(sbase + (uint32_t)(row * A_STRIDE_H + col) * 2,
                           gA + (size_t)row * DD + col);
            }
        }
    }

    int nb = 0;   // B chunks issued
    auto loadB = [&](int bj, int kc) {
        uint32_t boff = sbase + B_OFF + (uint32_t)(nb & 1) * B_CHUNK_BYTES;
        const __half* gB = g_zh + (size_t)(bj * BN) * DD + kc * BK;
        #pragma unroll
        for (int i = 0; i < 8; ++i) {
            int row = lrow + i * 16;
            cp_async16(boff + (uint32_t)(row * PADK + lcol8) * 2,
                       gB + (size_t)row * DD + lcol8);
        }
        ++nb;
        CP_COMMIT();
    };

    loadB(bjs[0], 0);   // A cp.asyncs folded into this first group

    // ldmatrix lane offsets
    uint32_t aLane[4], bLane[4];
    {
        int arow_lane = lane & 15;
        int akh       = lane >> 4;
        #pragma unroll
        for (int m = 0; m < 4; ++m) {
            int row = warpM * 64 + m * 16 + arow_lane;
            aLane[m] = (uint32_t)(row * A_STRIDE_H + akh * 8) * 2;
        }
        int bn  = (lane & 7) | ((lane >> 4) << 3);
        int bkh = (lane >> 3) & 1;
        #pragma unroll
        for (int q = 0; q < 4; ++q) {
            int n = warpN * 64 + q * 16 + bn;
            bLane[q] = (uint32_t)(n * PADK + bkh * 8) * 2;
        }
    }

    int r_base = warpM * 64 + (lane >> 2);
    int c_base = warpN * 64 + (lane & 3) * 2;
    const __half2 cmulh = __float2half2_rn(EX2_SCALE);
    uint32_t cmul_u = *(const uint32_t*)&cmulh;
    float* rowred = (float*)(smem + RED_OFF);          // [128][2]
    float* colred = (float*)(smem + RED_OFF) + 256;    // [128][2]

    int consumed = 0;
    for (int si = 0; si < ns; ++si) {
        int bj = bjs[si];
        int c0 = bj * BN;

        uint32_t acc[4][8][2];
        #pragma unroll
        for (int m = 0; m < 4; ++m)
            #pragma unroll
            for (int q = 0; q < 8; ++q) { acc[m][q][0] = 0u; acc[m][q][1] = 0u; }

        for (int kc = 0; kc < 4; ++kc) {
            bool pf = true;
            if (kc < 3)           loadB(bj, kc + 1);
            else if (si + 1 < ns) loadB(bjs[si + 1], 0);
            else                  pf = false;
            if (pf) { CP_WAIT(1); } else { CP_WAIT(0); }
            __syncthreads();

            uint32_t bbuf = sbase + B_OFF + (uint32_t)(consumed & 1) * B_CHUNK_BYTES;
            ++consumed;

            #pragma unroll
            for (int ks = 0; ks < BK / 16; ++ks) {
                int ksg = kc * 4 + ks;            // global kstep 0..15
                uint32_t a[4][4];
                #pragma unroll
                for (int m = 0; m < 4; ++m)
                    ldsm_x4(sbase + aLane[m] + ksg * 32, a[m][0], a[m][1], a[m][2], a[m][3]);
                uint32_t b[8][2];
                #pragma unroll
                for (int q = 0; q < 4; ++q)
                    ldsm_x4(bbuf + bLane[q] + ks * 32,
                            b[2*q][0], b[2*q][1], b[2*q+1][0], b[2*q+1][1]);
                #pragma unroll
                for (int m = 0; m < 4; ++m)
                    #pragma unroll
                    for (int q = 0; q < 8; ++q)
                        mma_f16acc(acc[m][q], a[m], b[q]);
            }
            __syncthreads();
        }

        // --- positive pairs ---
        if (bj == bi + 32) {
            #pragma unroll
            for (int m = 0; m < 4; ++m)
                #pragma unroll
                for (int q = 0; q < 8; ++q) {
                    float2 lo = __half22float2(*(__half2*)&acc[m][q][0]);
                    float2 hi = __half22float2(*(__half2*)&acc[m][q][1]);
                    int rl0 = r_base + m * 16, cl = c_base + q * 8;
                    if (rl0 == cl)         { g_pos[r0 + rl0] = lo.x;     g_pos[r0 + rl0 + NB] = lo.x; }
                    if (rl0 == cl + 1)     { g_pos[r0 + rl0] = lo.y;     g_pos[r0 + rl0 + NB] = lo.y; }
                    if (rl0 + 8 == cl)     { g_pos[r0 + rl0 + 8] = hi.x; g_pos[r0 + rl0 + 8 + NB] = hi.x; }
                    if (rl0 + 8 == cl + 1) { g_pos[r0 + rl0 + 8] = hi.y; g_pos[r0 + rl0 + 8 + NB] = hi.y; }
                }
        }

        // --- exp (f16x2) + HADD2 partial sums ---
        bool isDiag = (bj == bi);
        uint32_t racc0[4], racc1[4], cacc[8];
        #pragma unroll
        for (int m = 0; m < 4; ++m) { racc0[m] = 0u; racc1[m] = 0u; }
        #pragma unroll
        for (int q = 0; q < 8; ++q) cacc[q] = 0u;

        #pragma unroll
        for (int m = 0; m < 4; ++m)
            #pragma unroll
            for (int q = 0; q < 8; ++q) {
                uint32_t e0u = h2ex2(h2mul(acc[m][q][0], cmul_u));
                uint32_t e1u = h2ex2(h2mul(acc[m][q][1], cmul_u));
                if (isDiag) {
                    int rl0 = r_base + m * 16, cl = c_base + q * 8;
                    if (rl0 == cl)         e0u &= 0xFFFF0000u;
                    if (rl0 == cl + 1)     e0u &= 0x0000FFFFu;
                    if (rl0 + 8 == cl)     e1u &= 0xFFFF0000u;
                    if (rl0 + 8 == cl + 1) e1u &= 0x0000FFFFu;
                }
                racc0[m] = h2add(racc0[m], e0u);
                racc1[m] = h2add(racc1[m], e1u);
                cacc[q]  = h2add(cacc[q], h2add(e0u, e1u));
            }

        #pragma unroll
        for (int m = 0; m < 4; ++m) {
            float2 f0 = __half22float2(*(__half2*)&racc0[m]);
            float2 f1 = __half22float2(*(__half2*)&racc1[m]);
            float a0 = f0.x + f0.y;
            float a1 = f1.x + f1.y;
            a0 += __shfl_xor_sync(0xffffffffu, a0, 1);
            a0 += __shfl_xor_sync(0xffffffffu, a0, 2);
            a1 += __shfl_xor_sync(0xffffffffu, a1, 1);
            a1 += __shfl_xor_sync(0xffffffffu, a1, 2);
            if ((lane & 3) == 0) {
                int row = warpM * 64 + m * 16 + (lane >> 2);
                rowred[row * 2 + warpN]       = a0;
                rowred[(row + 8) * 2 + warpN] = a1;
            }
        }

        if (!isDiag) {
            #pragma unroll
            for (int q = 0; q < 8; ++q) {
                float2 fc = __half22float2(*(__half2*)&cacc[q]);
                float a0 = fc.x, a1 = fc.y;
                a0 += __shfl_xor_sync(0xffffffffu, a0, 4);
                a0 += __shfl_xor_sync(0xffffffffu, a0, 8);
                a0 += __shfl_xor_sync(0xffffffffu, a0, 16);
                a1 += __shfl_xor_sync(0xffffffffu, a1, 4);
                a1 += __shfl_xor_sync(0xffffffffu, a1, 8);
                a1 += __shfl_xor_sync(0xffffffffu, a1, 16);
                if (lane < 4) {
                    int n = warpN * 64 + q * 8 + lane * 2;
                    colred[n * 2 + warpM]       = a0;
                    colred[(n + 1) * 2 + warpM] = a1;
                }
            }
        }
        __syncthreads();

        g_partial[(size_t)bj * N2 + r0 + tid] = rowred[tid * 2] + rowred[tid * 2 + 1];
        if (!isDiag)
            g_partial[(size_t)bi * N2 + c0 + tid] = colred[tid * 2] + colred[tid * 2 + 1];
        __syncthreads();
    }
}

// ---------------------------------------------------------------------------
// Kernel 3: per-row loss + fused mean.
// ---------------------------------------------------------------------------
__global__ void k_rowloss(float* __restrict__ out) {
    __shared__ float st[8][68];
    __shared__ float sm[256];
    __shared__ int isLast;
    int tid = threadIdx.x;
    int r0  = blockIdx.x * 8;

    {
        int s  = tid >> 2;
        int ro = (tid & 3) * 2;
        float2 v = *(const float2*)&g_partial[(size_t)s * N2 + r0 + ro];
        st[ro][s]     = v.x;
        st[ro + 1][s] = v.y;
    }
    __syncthreads();

    int w    = tid >> 5;
    int lane = tid & 31;
    float S = st[w][lane] + st[w][lane + 32];
    #pragma unroll
    for (int o = 16; o > 0; o >>= 1) S += __shfl_xor_sync(0xffffffffu, S, o);

    if (lane == 0) {
        float ep = __expf(INV_TEMP * g_pos[r0 + w]);
        g_loss[r0 + w] = -logf(ep / (ep + S));
    }
    __threadfence();
    __syncthreads();
    if (tid == 0) {
        int old = atomicAdd(&g_sem, 1);
        isLast = (old == gridDim.x - 1);
    }
    __syncthreads();
    if (isLast) {
        float s = 0.f;
        #pragma unroll
        for (int i = 0; i < 8; ++i) {
            float4 v = *(const float4*)&g_loss[(tid + i * 256) * 4];
            s += v.x + v.y + v.z + v.w;
        }
        sm[tid] = s;
        __syncthreads();
        for (int stp = 128; stp > 0; stp >>= 1) {
            if (tid < stp) sm[tid] += sm[tid + stp];
            __syncthreads();
        }
        if (tid == 0) { out[0] = sm[0] * (1.0f / (float)N2); g_sem = 0; }
    }
}

extern "C" void kernel_launch(void* const* d_in, const int* in_sizes, int n_in,
                              void* d_out, int out_size) {
    const float* xi = (const float*)d_in[0];
    const float* xj = (const float*)d_in[1];
    float* out = (float*)d_out;

    cudaFuncSetAttribute(k_expsum_mma, cudaFuncAttributeMaxDynamicSharedMemorySize, SMEM_TOTAL);

    k_normalize<<<512, 256>>>(xi, xj);
    k_expsum_mma<<<NCTA, 128, SMEM_TOTAL>>>();
    k_rowloss<<<N2 / 8, 256>>>(out);
}

// round 13
// speedup vs baseline: 1.1339x; 1.1339x over previous
#include <cuda_runtime.h>
#include <cuda_fp16.h>
#include <cstdint>

#define NB 4096
#define N2 8192
#define DD 256
#define INV_TEMP 2.0f
#define EX2_SCALE 2.885390081777927f   // 2 * log2(e)

#define BM 128
#define BK 64
#define NSTRIPE 64
#define NCTA 1056                // sum over bi of (32 - bi/2)
#define PADK 72                  // halves per smem row (144B)

// smem: A bufs @0,@18432 ; B bufs @36864,@73728 ; total 110592 B
#define A_CHUNK_BYTES 18432      // 128 * 72 * 2
#define B_CHUNK_BYTES 36864      // 256 * 72 * 2
#define B_OFF 36864
#define SMEM_TOTAL 110592

// Scratch (static device globals — no allocation)
__device__ __half         g_zh[(size_t)N2 * DD];            // normalized rows fp16
__device__ float          g_partial[(size_t)NSTRIPE * N2];  // [stripe][row]
__device__ float          g_pos[N2];
__device__ float          g_loss[N2];
__device__ int            g_sem;

__device__ __forceinline__ uint32_t smem_u32(const void* p) {
    return (uint32_t)__cvta_generic_to_shared(p);
}
__device__ __forceinline__ void ldsm_x4(uint32_t addr, uint32_t& r0, uint32_t& r1,
                                        uint32_t& r2, uint32_t& r3) {
    asm volatile("ldmatrix.sync.aligned.m8n8.x4.shared.b16 {%0,%1,%2,%3}, [%4];"
                 : "=r"(r0), "=r"(r1), "=r"(r2), "=r"(r3) : "r"(addr));
}
__device__ __forceinline__ void mma_f16acc(uint32_t* d, const uint32_t* a, const uint32_t* b) {
    asm volatile(
        "mma.sync.aligned.m16n8k16.row.col.f16.f16.f16.f16 "
        "{%0,%1}, {%2,%3,%4,%5}, {%6,%7}, {%0,%1};"
        : "+r"(d[0]), "+r"(d[1])
        : "r"(a[0]), "r"(a[1]), "r"(a[2]), "r"(a[3]), "r"(b[0]), "r"(b[1]));
}
__device__ __forceinline__ uint32_t h2ex2(uint32_t x) {
    uint32_t y;
    asm("ex2.approx.f16x2 %0, %1;" : "=r"(y) : "r"(x));
    return y;
}
__device__ __forceinline__ uint32_t h2mul(uint32_t a, uint32_t b) {
    __half2 r = __hmul2(*(__half2*)&a, *(__half2*)&b);
    return *(uint32_t*)&r;
}
__device__ __forceinline__ uint32_t h2add(uint32_t a, uint32_t b) {
    __half2 r = __hadd2(*(__half2*)&a, *(__half2*)&b);
    return *(uint32_t*)&r;
}
__device__ __forceinline__ void cp_async16(uint32_t smem_addr, const void* gptr) {
    asm volatile("cp.async.cg.shared.global [%0], [%1], 16;"
                 :: "r"(smem_addr), "l"(gptr) : "memory");
}
#define CP_COMMIT() asm volatile("cp.async.commit_group;" ::: "memory")
#define CP_WAIT(n)  asm volatile("cp.async.wait_group %0;" :: "n"(n) : "memory")

// ---------------------------------------------------------------------------
// Kernel 1: L2-normalize. One warp handles rows (w, w+NB).
// ---------------------------------------------------------------------------
__global__ void k_normalize(const float* __restrict__ xi, const float* __restrict__ xj) {
    int w    = blockIdx.x * 8 + (threadIdx.x >> 5);
    int lane = threadIdx.x & 31;
    const float* sa = xi + (size_t)w * DD;
    const float* sb = xj + (size_t)w * DD;
    float4 a0 = *(const float4*)(sa + lane * 4);
    float4 a1 = *(const float4*)(sa + 128 + lane * 4);
    float4 b0 = *(const float4*)(sb + lane * 4);
    float4 b1 = *(const float4*)(sb + 128 + lane * 4);
    float s_a = a0.x*a0.x + a0.y*a0.y + a0.z*a0.z + a0.w*a0.w
              + a1.x*a1.x + a1.y*a1.y + a1.z*a1.z + a1.w*a1.w;
    float s_b = b0.x*b0.x + b0.y*b0.y + b0.z*b0.z + b0.w*b0.w
              + b1.x*b1.x + b1.y*b1.y + b1.z*b1.z + b1.w*b1.w;
    #pragma unroll
    for (int o = 16; o > 0; o >>= 1) {
        s_a += __shfl_xor_sync(0xffffffffu, s_a, o);
        s_b += __shfl_xor_sync(0xffffffffu, s_b, o);
    }
    float ia = 1.0f / fmaxf(sqrtf(s_a), 1e-12f);
    float ib = 1.0f / fmaxf(sqrtf(s_b), 1e-12f);

    __half2 h[4];
    h[0] = __floats2half2_rn(a0.x * ia, a0.y * ia);
    h[1] = __floats2half2_rn(a0.z * ia, a0.w * ia);
    h[2] = __floats2half2_rn(a1.x * ia, a1.y * ia);
    h[3] = __floats2half2_rn(a1.z * ia, a1.w * ia);
    __half* da = g_zh + (size_t)w * DD;
    *(uint2*)(da + lane * 4)       = make_uint2(*(uint32_t*)&h[0], *(uint32_t*)&h[1]);
    *(uint2*)(da + 128 + lane * 4) = make_uint2(*(uint32_t*)&h[2], *(uint32_t*)&h[3]);

    h[0] = __floats2half2_rn(b0.x * ib, b0.y * ib);
    h[1] = __floats2half2_rn(b0.z * ib, b0.w * ib);
    h[2] = __floats2half2_rn(b1.x * ib, b1.y * ib);
    h[3] = __floats2half2_rn(b1.z * ib, b1.w * ib);
    __half* db = g_zh + (size_t)(w + NB) * DD;
    *(uint2*)(db + lane * 4)       = make_uint2(*(uint32_t*)&h[0], *(uint32_t*)&h[1]);
    *(uint2*)(db + 128 + lane * 4) = make_uint2(*(uint32_t*)&h[2], *(uint32_t*)&h[3]);
}

// ---------------------------------------------------------------------------
// Kernel 2: 128x256 CTA tile (both stripes of a column pair), 8 warps in
// 2(M) x 4(N), warp tile 64x64. K double-buffered in 64-chunks.
// ---------------------------------------------------------------------------
__global__ __launch_bounds__(256, 2) void k_expsum_mma() {
    extern __shared__ char smem[];
    int tid   = threadIdx.x;
    int lane  = tid & 31;
    int wid   = tid >> 5;          // 0..7
    int warpM = wid >> 2;          // 0..1
    int warpN = wid & 3;           // 0..3

    // Decode blockIdx.x -> (bi, pair t). Pairs per bi: 32 - (bi>>1).
    int rem = blockIdx.x;
    int bi = 0;
    while (true) {
        int p = 32 - (bi >> 1);
        if (rem < p) break;
        rem -= p; ++bi;
    }
    int t  = (bi >> 1) + rem;
    int r0 = bi * BM;
    int cbase = 2 * t * 128;            // global col of CTA's first stripe
    int bjW = 2 * t + (warpN >> 1);     // this warp's stripe index

    uint32_t sbase = smem_u32(smem);
    int lrow  = tid >> 3;               // 0..31
    int lcol8 = (tid & 7) * 8;          // halves

    auto load_chunk = [&](int kc) {
        uint32_t abuf = sbase + (uint32_t)(kc & 1) * A_CHUNK_BYTES;
        uint32_t bbuf = sbase + B_OFF + (uint32_t)(kc & 1) * B_CHUNK_BYTES;
        const __half* gA = g_zh + (size_t)r0 * DD + kc * BK;
        const __half* gB = g_zh + (size_t)cbase * DD + kc * BK;
        #pragma unroll
        for (int i = 0; i < 4; ++i) {
            int row = lrow + i * 32;
            cp_async16(abuf + (uint32_t)(row * PADK + lcol8) * 2,
                       gA + (size_t)row * DD + lcol8);
        }
        #pragma unroll
        for (int i = 0; i < 8; ++i) {
            int row = lrow + i * 32;
            cp_async16(bbuf + (uint32_t)(row * PADK + lcol8) * 2,
                       gB + (size_t)row * DD + lcol8);
        }
        CP_COMMIT();
    };

    uint32_t aLane[4], bLane[4];
    {
        int arow_lane = lane & 15;
        int akh       = lane >> 4;
        #pragma unroll
        for (int m = 0; m < 4; ++m) {
            int row = warpM * 64 + m * 16 + arow_lane;
            aLane[m] = (uint32_t)(row * PADK + akh * 8) * 2;
        }
        int bn  = (lane & 7) | ((lane >> 4) << 3);
        int bkh = (lane >> 3) & 1;
        #pragma unroll
        for (int q = 0; q < 4; ++q) {
            int n = warpN * 64 + q * 16 + bn;   // 0..255
            bLane[q] = (uint32_t)(n * PADK + bkh * 8) * 2;
        }
    }

    uint32_t acc[4][8][2];
    #pragma unroll
    for (int m = 0; m < 4; ++m)
        #pragma unroll
        for (int q = 0; q < 8; ++q) { acc[m][q][0] = 0u; acc[m][q][1] = 0u; }

    load_chunk(0);

    for (int kc = 0; kc < 4; ++kc) {
        if (kc < 3) { load_chunk(kc + 1); CP_WAIT(1); }
        else        { CP_WAIT(0); }
        __syncthreads();

        uint32_t abuf = sbase + (uint32_t)(kc & 1) * A_CHUNK_BYTES;
        uint32_t bbuf = sbase + B_OFF + (uint32_t)(kc & 1) * B_CHUNK_BYTES;

        #pragma unroll
        for (int ks = 0; ks < BK / 16; ++ks) {
            uint32_t a[4][4];
            #pragma unroll
            for (int m = 0; m < 4; ++m)
                ldsm_x4(abuf + aLane[m] + ks * 32, a[m][0], a[m][1], a[m][2], a[m][3]);
            #pragma unroll
            for (int qp = 0; qp < 4; ++qp) {
                uint32_t b0r, b1r, b2r, b3r;
                ldsm_x4(bbuf + bLane[qp] + ks * 32, b0r, b1r, b2r, b3r);
                uint32_t bq[2][2] = {{b0r, b1r}, {b2r, b3r}};
                #pragma unroll
                for (int h = 0; h < 2; ++h)
                    #pragma unroll
                    for (int m = 0; m < 4; ++m)
                        mma_f16acc(acc[m][2*qp + h], a[m], bq[h]);
            }
        }
        __syncthreads();
    }

    // Per-thread fragment coordinates (within warp's 64x64 tile / 128-stripe).
    int r_base = warpM * 64 + (lane >> 2);              // + m*16 (+8)
    int c_base = (warpN & 1) * 64 + (lane & 3) * 2;     // + q*8, within stripe

    // --- positive pairs: stripe bjW == bi + 32 has pos on its local diagonal ---
    if (bjW == bi + 32) {
        #pragma unroll
        for (int m = 0; m < 4; ++m)
            #pragma unroll
            for (int q = 0; q < 8; ++q) {
                float2 lo = __half22float2(*(__half2*)&acc[m][q][0]);
                float2 hi = __half22float2(*(__half2*)&acc[m][q][1]);
                int rl0 = r_base + m * 16, cl = c_base + q * 8;
                if (rl0 == cl)         { g_pos[r0 + rl0] = lo.x;     g_pos[r0 + rl0 + NB] = lo.x; }
                if (rl0 == cl + 1)     { g_pos[r0 + rl0] = lo.y;     g_pos[r0 + rl0 + NB] = lo.y; }
                if (rl0 + 8 == cl)     { g_pos[r0 + rl0 + 8] = hi.x; g_pos[r0 + rl0 + 8 + NB] = hi.x; }
                if (rl0 + 8 == cl + 1) { g_pos[r0 + rl0 + 8] = hi.y; g_pos[r0 + rl0 + 8 + NB] = hi.y; }
            }
    }

    // --- exp (f16x2) + HADD2 partial sums ---
    bool isDiag = (bjW == bi);
    const __half2 cmulh = __float2half2_rn(EX2_SCALE);
    uint32_t cmul_u = *(const uint32_t*)&cmulh;

    uint32_t racc0[4], racc1[4], cacc[8];
    #pragma unroll
    for (int m = 0; m < 4; ++m) { racc0[m] = 0u; racc1[m] = 0u; }
    #pragma unroll
    for (int q = 0; q < 8; ++q) cacc[q] = 0u;

    #pragma unroll
    for (int m = 0; m < 4; ++m)
        #pragma unroll
        for (int q = 0; q < 8; ++q) {
            uint32_t e0u = h2ex2(h2mul(acc[m][q][0], cmul_u));
            uint32_t e1u = h2ex2(h2mul(acc[m][q][1], cmul_u));
            if (isDiag) {
                int rl0 = r_base + m * 16, cl = c_base + q * 8;
                if (rl0 == cl)         e0u &= 0xFFFF0000u;
                if (rl0 == cl + 1)     e0u &= 0x0000FFFFu;
                if (rl0 + 8 == cl)     e1u &= 0xFFFF0000u;
                if (rl0 + 8 == cl + 1) e1u &= 0x0000FFFFu;
            }
            racc0[m] = h2add(racc0[m], e0u);
            racc1[m] = h2add(racc1[m], e1u);
            cacc[q]  = h2add(cacc[q], h2add(e0u, e1u));
        }

    // Red arrays alias the (dead) A buffers.
    float* rowred = (float*)smem;            // [2 stripes][128 rows][2 halves]
    float* colred = (float*)smem + 512;      // [256 cols][2 warpM]

    int stripe = warpN >> 1;
    #pragma unroll
    for (int m = 0; m < 4; ++m) {
        float2 f0 = __half22float2(*(__half2*)&racc0[m]);
        float2 f1 = __half22float2(*(__half2*)&racc1[m]);
        float a0 = f0.x + f0.y;
        float a1 = f1.x + f1.y;
        a0 += __shfl_xor_sync(0xffffffffu, a0, 1);
        a0 += __shfl_xor_sync(0xffffffffu, a0, 2);
        a1 += __shfl_xor_sync(0xffffffffu, a1, 1);
        a1 += __shfl_xor_sync(0xffffffffu, a1, 2);
        if ((lane & 3) == 0) {
            int row = warpM * 64 + m * 16 + (lane >> 2);
            rowred[(stripe * 128 + row) * 2 + (warpN & 1)]       = a0;
            rowred[(stripe * 128 + row + 8) * 2 + (warpN & 1)]   = a1;
        }
    }

    #pragma unroll
    for (int q = 0; q < 8; ++q) {
        float2 fc = __half22float2(*(__half2*)&cacc[q]);
        float a0 = fc.x, a1 = fc.y;
        a0 += __shfl_xor_sync(0xffffffffu, a0, 4);
        a0 += __shfl_xor_sync(0xffffffffu, a0, 8);
        a0 += __shfl_xor_sync(0xffffffffu, a0, 16);
        a1 += __shfl_xor_sync(0xffffffffu, a1, 4);
        a1 += __shfl_xor_sync(0xffffffffu, a1, 8);
        a1 += __shfl_xor_sync(0xffffffffu, a1, 16);
        if (lane < 4) {
            int n = warpN * 64 + q * 8 + lane * 2;   // 0..255
            colred[n * 2 + warpM]       = a0;
            colred[(n + 1) * 2 + warpM] = a1;
        }
    }
    __syncthreads();

    // Stores (coalesced). Skip lower-triangle stripe (odd bi, first pair).
    {
        int s  = tid >> 7;            // stripe 0/1
        int rr = tid & 127;
        int bjS = 2 * t + s;
        if (bjS >= bi)
            g_partial[(size_t)bjS * N2 + r0 + rr] =
                rowred[(s * 128 + rr) * 2] + rowred[(s * 128 + rr) * 2 + 1];
        if (bjS > bi)                 // non-diag upper: col sums
            g_partial[(size_t)bi * N2 + cbase + tid] =
                colred[tid * 2] + colred[tid * 2 + 1];
    }
}

// ---------------------------------------------------------------------------
// Kernel 3: per-row loss + fused mean.
// ---------------------------------------------------------------------------
__global__ void k_rowloss(float* __restrict__ out) {
    __shared__ float st[8][68];
    __shared__ float sm[256];
    __shared__ int isLast;
    int tid = threadIdx.x;
    int r0  = blockIdx.x * 8;

    {
        int s  = tid >> 2;
        int ro = (tid & 3) * 2;
        float2 v = *(const float2*)&g_partial[(size_t)s * N2 + r0 + ro];
        st[ro][s]     = v.x;
        st[ro + 1][s] = v.y;
    }
    __syncthreads();

    int w    = tid >> 5;
    int lane = tid & 31;
    float S = st[w][lane] + st[w][lane + 32];
    #pragma unroll
    for (int o = 16; o > 0; o >>= 1) S += __shfl_xor_sync(0xffffffffu, S, o);

    if (lane == 0) {
        float ep = __expf(INV_TEMP * g_pos[r0 + w]);
        g_loss[r0 + w] = -logf(ep / (ep + S));
    }
    __threadfence();
    __syncthreads();
    if (tid == 0) {
        int old = atomicAdd(&g_sem, 1);
        isLast = (old == gridDim.x - 1);
    }
    __syncthreads();
    if (isLast) {
        float s = 0.f;
        #pragma unroll
        for (int i = 0; i < 8; ++i) {
            float4 v = *(const float4*)&g_loss[(tid + i * 256) * 4];
            s += v.x + v.y + v.z + v.w;
        }
        sm[tid] = s;
        __syncthreads();
        for (int stp = 128; stp > 0; stp >>= 1) {
            if (tid < stp) sm[tid] += sm[tid + stp];
            __syncthreads();
        }
        if (tid == 0) { out[0] = sm[0] * (1.0f / (float)N2); g_sem = 0; }
    }
}

extern "C" void kernel_launch(void* const* d_in, const int* in_sizes, int n_in,
                              void* d_out, int out_size) {
    const float* xi = (const float*)d_in[0];
    const float* xj = (const float*)d_in[1];
    float* out = (float*)d_out;

    cudaFuncSetAttribute(k_expsum_mma, cudaFuncAttributeMaxDynamicSharedMemorySize, SMEM_TOTAL);

    k_normalize<<<512, 256>>>(xi, xj);
    k_expsum_mma<<<NCTA, 256, SMEM_TOTAL>>>();
    k_rowloss<<<N2 / 8, 256>>>(out);
}